// round 16
// baseline (speedup 1.0000x reference)
#include <cuda_runtime.h>
#include <cstdint>
#include <math.h>

#define NN 50000
#define NE 800000
#define NG 64
#define NB_SCAN 196   // ceil(NN/256)

// ---------------- scratch (static __device__, no allocs) ----------------
__device__ __align__(16) float d_zb[NN * 128];    // [base(64) | z(64)] per node
__device__ __align__(16) float d_aggr[NN * 256];  // [mean|min|max|std]
__device__ __align__(16) float d_xa[NN * 64];
__device__ __align__(16) float d_xb[NN * 64];
__device__ int   d_deg[NN];
__device__ int   d_off[NN + 1];
__device__ int   d_cur[NN];
__device__ int   d_csr[NE];
__device__ float d_amp[NN];
__device__ float d_att[NN];
__device__ float d_pool[NG * 64];
__device__ int   d_cnt[NG];
__device__ int   d_part[NB_SCAN];
__device__ float d_logpart[NB_SCAN];
// presplit tf32 hi/lo weights
__device__ __align__(16) uint32_t d_wph[3 * 64 * 832];
__device__ __align__(16) uint32_t d_wpl[3 * 64 * 832];
__device__ __align__(16) uint32_t d_pwh[3 * 128 * 64];
__device__ __align__(16) uint32_t d_pwl[3 * 128 * 64];
__device__ __align__(16) uint32_t d_lwh[3 * 64 * 64];
__device__ __align__(16) uint32_t d_lwl[3 * 64 * 64];

// ---------------- mma.sync tf32 helpers (sm_80+ baseline PTX) ----------
__device__ __forceinline__ uint32_t f2tf(float x) {
    uint32_t u;
    asm("cvt.rna.tf32.f32 %0, %1;" : "=r"(u) : "f"(x));
    return u;
}

// RNA split: v = hi + lo, hi round-to-nearest tf32 (unbiased)
__device__ __forceinline__ void tf32_split(float v, uint32_t& hi, uint32_t& lo) {
    uint32_t h = f2tf(v);
    hi = h;
    lo = f2tf(v - __uint_as_float(h));
}

__device__ __forceinline__ void mma_tf32(float& c0, float& c1, float& c2, float& c3,
                                         uint32_t a0, uint32_t a1, uint32_t a2, uint32_t a3,
                                         uint32_t b0, uint32_t b1) {
    asm volatile("mma.sync.aligned.m16n8k8.row.col.f32.tf32.tf32.f32 "
        "{%0,%1,%2,%3}, {%4,%5,%6,%7}, {%8,%9}, {%0,%1,%2,%3};"
        : "+f"(c0), "+f"(c1), "+f"(c2), "+f"(c3)
        : "r"(a0), "r"(a1), "r"(a2), "r"(a3), "r"(b0), "r"(b1));
}

// 3-term 3xTF32 accumulate
#define MMA3(C, ah0, ah1, ah2, ah3, al0, al1, al2, al3, bh0, bh1, bl0, bl1) do { \
    mma_tf32(C[0], C[1], C[2], C[3], ah0, ah1, ah2, ah3, bh0, bh1); \
    mma_tf32(C[0], C[1], C[2], C[3], ah0, ah1, ah2, ah3, bl0, bl1); \
    mma_tf32(C[0], C[1], C[2], C[3], al0, al1, al2, al3, bh0, bh1); \
} while (0)

// ---------------- setup kernels ----------------
__global__ void k_init() {
    int i = blockIdx.x * blockDim.x + threadIdx.x;
    if (i < NN) d_deg[i] = 0;
    if (i < NG * 64) d_pool[i] = 0.f;
    if (i < NG) d_cnt[i] = 0;
}

__global__ void k_degree(const int* __restrict__ dst) {
    int e = blockIdx.x * blockDim.x + threadIdx.x;
    if (e < NE) atomicAdd(&d_deg[dst[e]], 1);
}

// split all weights into tf32 hi/lo once
__global__ void k_splitw(const float* __restrict__ pre_w,
                         const float* __restrict__ post_w,
                         const float* __restrict__ lin_w) {
    int stride = gridDim.x * blockDim.x;
    int i0 = blockIdx.x * blockDim.x + threadIdx.x;
    for (int t = i0; t < 3 * 64 * 832; t += stride) {
        uint32_t h, l;
        tf32_split(post_w[t], h, l);
        d_wph[t] = h; d_wpl[t] = l;
    }
    for (int t = i0; t < 3 * 128 * 64; t += stride) {
        int l = t >> 13, r = t & 8191;
        int j = r >> 6, k = r & 63;
        int jj = j & 63, off = (j >= 64) ? 64 : 0;
        float v = pre_w[l * 8192 + jj * 128 + off + k];
        uint32_t h, lo;
        tf32_split(v, h, lo);
        d_pwh[t] = h; d_pwl[t] = lo;
    }
    for (int t = i0; t < 3 * 64 * 64; t += stride) {
        uint32_t h, l;
        tf32_split(lin_w[t], h, l);
        d_lwh[t] = h; d_lwl[t] = l;
    }
}

// per-block sums of degree + log-degree
__global__ void k_scan1() {
    __shared__ int ssum[8];
    __shared__ float slog[8];
    int tid = threadIdx.x, lane = tid & 31, w = tid >> 5;
    int i = blockIdx.x * 256 + tid;
    int v = (i < NN) ? d_deg[i] : 0;
    float l = (i < NN) ? logf((float)v + 1.f) : 0.f;
    int s = v;
    #pragma unroll
    for (int d = 16; d; d >>= 1) {
        s += __shfl_xor_sync(0xffffffffu, s, d);
        l += __shfl_xor_sync(0xffffffffu, l, d);
    }
    if (lane == 0) { ssum[w] = s; slog[w] = l; }
    __syncthreads();
    if (tid == 0) {
        int t = 0; float lt = 0.f;
        #pragma unroll
        for (int k = 0; k < 8; k++) { t += ssum[k]; lt += slog[k]; }
        d_part[blockIdx.x] = t;
        d_logpart[blockIdx.x] = lt;
    }
}

// per-element offsets + amp/att scalars; block prefix + avglog computed redundantly
__global__ void k_scan3() {
    __shared__ int ws[8];
    __shared__ int s_boff;
    __shared__ float s_avg;
    int tid = threadIdx.x, lane = tid & 31, w = tid >> 5;
    int bid = blockIdx.x;
    if (w == 0) {
        int acc = 0;
        for (int k = lane; k < bid; k += 32) acc += d_part[k];
        #pragma unroll
        for (int d = 16; d; d >>= 1) acc += __shfl_xor_sync(0xffffffffu, acc, d);
        if (lane == 0) s_boff = acc;
    }
    if (w == 1 && lane == 0) {
        float s = 0.f;
        for (int k = 0; k < NB_SCAN; k++) s += d_logpart[k];
        s_avg = s / (float)NN;
    }
    int i = bid * 256 + tid;
    int v = (i < NN) ? d_deg[i] : 0;
    int x = v;
    #pragma unroll
    for (int d = 1; d < 32; d <<= 1) {
        int t = __shfl_up_sync(0xffffffffu, x, d);
        if (lane >= d) x += t;
    }
    if (lane == 31) ws[w] = x;
    __syncthreads();
    if (tid == 0) {
        int acc = 0;
        #pragma unroll
        for (int k = 0; k < 8; k++) { int t = ws[k]; ws[k] = acc; acc += t; }
    }
    __syncthreads();
    int excl = s_boff + ws[w] + x - v;
    if (i < NN) {
        d_off[i] = excl;
        d_cur[i] = excl;
        float avg = s_avg;
        float degf = (float)(v > 1 ? v : 1);
        float ld = logf(degf + 1.f);
        d_amp[i] = ld / avg;
        d_att[i] = avg / ld;
    }
    if (i == 0) d_off[NN] = NE;
}

__global__ void k_fill(const int* __restrict__ src, const int* __restrict__ dst) {
    int e = blockIdx.x * blockDim.x + threadIdx.x;
    if (e < NE) {
        int dn = dst[e];
        int p = atomicAdd(&d_cur[dn], 1);
        d_csr[p] = src[e];
    }
}

// ---------------- pre GEMM via 3xTF32 mma (layer 0 only) ----------
// smem: [0,256) bias | [2048,20480) Ah 128x36 | [20480,38912) Al
//       [38912,57344) Bh 128x36 | [57344,75776) Bl
#define PRE_SMEM 75776

__global__ __launch_bounds__(256) void k_pre_mma(const float* __restrict__ X,
                                                 const uint32_t* __restrict__ pwh,
                                                 const uint32_t* __restrict__ pwl,
                                                 const float* __restrict__ B) {
    extern __shared__ char smem[];
    float* s_bias = (float*)(smem + 0);
    uint32_t* sAh = (uint32_t*)(smem + 2048);
    uint32_t* sAl = (uint32_t*)(smem + 20480);
    uint32_t* sBh = (uint32_t*)(smem + 38912);
    uint32_t* sBl = (uint32_t*)(smem + 57344);

    int tid = threadIdx.x;
    int lane = tid & 31, wid = tid >> 5;
    int gid = lane >> 2, tq = lane & 3;
    int mrow = wid * 16;
    int row0 = blockIdx.x * 128;
    if (tid < 64) s_bias[tid] = B[tid];

    float c[16][4];
    #pragma unroll
    for (int nt = 0; nt < 16; nt++)
        #pragma unroll
        for (int q = 0; q < 4; q++) c[nt][q] = 0.f;

    int rr = tid >> 3, f = tid & 7;

    for (int ch = 0; ch < 2; ch++) {
        __syncthreads();
        #pragma unroll
        for (int it = 0; it < 4; it++) {
            int r = rr + it * 32;
            int gr = row0 + r;
            float4 v = make_float4(0.f, 0.f, 0.f, 0.f);
            if (gr < NN) v = *(const float4*)(X + (size_t)gr * 64 + ch * 32 + f * 4);
            uint32_t h0, l0, h1, l1, h2, l2, h3, l3;
            tf32_split(v.x, h0, l0); tf32_split(v.y, h1, l1);
            tf32_split(v.z, h2, l2); tf32_split(v.w, h3, l3);
            int base = r * 36 + f * 4;
            *(uint4*)&sAh[base] = make_uint4(h0, h1, h2, h3);
            *(uint4*)&sAl[base] = make_uint4(l0, l1, l2, l3);
        }
        #pragma unroll
        for (int it = 0; it < 4; it++) {
            int idx = tid + it * 256;
            int j = idx >> 3, fb = idx & 7;
            int src = j * 64 + ch * 32 + fb * 4;
            uint4 h = *(const uint4*)(pwh + src);
            uint4 l = *(const uint4*)(pwl + src);
            int dst = j * 36 + fb * 4;
            *(uint4*)&sBh[dst] = h;
            *(uint4*)&sBl[dst] = l;
        }
        __syncthreads();
        #pragma unroll
        for (int ks = 0; ks < 4; ks++) {
            int k0 = ks * 8;
            int ra = (mrow + gid) * 36 + k0 + tq;
            int rb = (mrow + gid + 8) * 36 + k0 + tq;
            uint32_t ah0 = sAh[ra], ah1 = sAh[rb], ah2 = sAh[ra + 4], ah3 = sAh[rb + 4];
            uint32_t al0 = sAl[ra], al1 = sAl[rb], al2 = sAl[ra + 4], al3 = sAl[rb + 4];
            #pragma unroll
            for (int nt = 0; nt < 16; nt++) {
                int nb = (nt * 8 + gid) * 36 + k0 + tq;
                uint32_t bh0 = sBh[nb], bh1 = sBh[nb + 4];
                uint32_t bl0 = sBl[nb], bl1 = sBl[nb + 4];
                MMA3(c[nt], ah0, ah1, ah2, ah3, al0, al1, al2, al3, bh0, bh1, bl0, bl1);
            }
        }
    }
    int grow0 = row0 + mrow + gid;
    int grow1 = grow0 + 8;
    #pragma unroll
    for (int nt = 0; nt < 16; nt++) {
        int col = nt * 8 + 2 * tq;
        float b0 = (col < 64) ? s_bias[col] : 0.f;
        float b1 = (col < 64) ? s_bias[col + 1] : 0.f;
        if (grow0 < NN)
            *(float2*)(d_zb + (size_t)grow0 * 128 + col) = make_float2(c[nt][0] + b0, c[nt][1] + b1);
        if (grow1 < NN)
            *(float2*)(d_zb + (size_t)grow1 * 128 + col) = make_float2(c[nt][2] + b0, c[nt][3] + b1);
    }
}

// ---------------- aggregation: 1 warp per node, 8-way, z-only stats ----------
__global__ __launch_bounds__(256) void k_aggr() {
    int gw = (blockIdx.x * blockDim.x + threadIdx.x) >> 5;
    int lane = threadIdx.x & 31;
    if (gw >= NN) return;
    int beg = d_off[gw], end = d_off[gw + 1];
    float2 base = *(const float2*)(d_zb + (size_t)gw * 128 + lane * 2);
    float s1x = 0.f, s1y = 0.f, s2x = 0.f, s2y = 0.f;
    float mnx = INFINITY, mny = INFINITY, mxx = -INFINITY, mxy = -INFINITY;
    int e = beg;
    for (; e + 8 <= end; e += 8) {
        int idx[8];
        #pragma unroll
        for (int u = 0; u < 8; u++) idx[u] = d_csr[e + u];
        float2 z[8];
        #pragma unroll
        for (int u = 0; u < 8; u++)
            z[u] = *(const float2*)(d_zb + (size_t)idx[u] * 128 + 64 + lane * 2);
        #pragma unroll
        for (int u = 0; u < 8; u++) {
            s1x += z[u].x; s2x += z[u].x * z[u].x;
            mnx = fminf(mnx, z[u].x); mxx = fmaxf(mxx, z[u].x);
            s1y += z[u].y; s2y += z[u].y * z[u].y;
            mny = fminf(mny, z[u].y); mxy = fmaxf(mxy, z[u].y);
        }
    }
    for (; e < end; e++) {
        int s = d_csr[e];
        float2 z = *(const float2*)(d_zb + (size_t)s * 128 + 64 + lane * 2);
        s1x += z.x; s2x += z.x * z.x; mnx = fminf(mnx, z.x); mxx = fmaxf(mxx, z.x);
        s1y += z.y; s2y += z.y * z.y; mny = fminf(mny, z.y); mxy = fmaxf(mxy, z.y);
    }
    int drI = end - beg;
    float* a = d_aggr + (size_t)gw * 256;
    if (drI == 0) {
        float sv = sqrtf(1e-5f);
        *(float2*)(a + lane * 2)       = make_float2(0.f, 0.f);
        *(float2*)(a + 64 + lane * 2)  = make_float2(0.f, 0.f);
        *(float2*)(a + 128 + lane * 2) = make_float2(0.f, 0.f);
        *(float2*)(a + 192 + lane * 2) = make_float2(sv, sv);
        return;
    }
    float deg = (float)drI;
    float mzx = s1x / deg, mzy = s1y / deg;
    float meanx = base.x + mzx, meany = base.y + mzy;
    float stdx = sqrtf(fmaxf(s2x / deg - mzx * mzx, 0.f) + 1e-5f);
    float stdy = sqrtf(fmaxf(s2y / deg - mzy * mzy, 0.f) + 1e-5f);
    *(float2*)(a + lane * 2)       = make_float2(meanx, meany);
    *(float2*)(a + 64 + lane * 2)  = make_float2(base.x + mnx, base.y + mny);
    *(float2*)(a + 128 + lane * 2) = make_float2(base.x + mxx, base.y + mxy);
    *(float2*)(a + 192 + lane * 2) = make_float2(stdx, stdy);
}

// ---------------- post+lin (+fused next-layer pre) via 3xTF32 mma ----------
// smem: [0,256) bp | [256,512) bl | [512,1024) amp | [1024,1536) att | [1536,1792) pre-bias
//  [2048,20480) Ah 128x36 | [20480,38912) Al
//  [38912,75776) B region (contiguous 9216 u32):
//    phase1/2: Bh 3x64x36 at +0, Bl 1x64x36 at +6912
//    fused pre: Bh 128x36 at +0, Bl 128x36 at +4608
#define POST_SMEM 75776

__global__ __launch_bounds__(256) void k_post_mma_sync(const float* __restrict__ X,
                                                       const uint32_t* __restrict__ wph,
                                                       const uint32_t* __restrict__ wpl,
                                                       const float* __restrict__ bp,
                                                       const uint32_t* __restrict__ lwh,
                                                       const uint32_t* __restrict__ lwl,
                                                       const float* __restrict__ bl,
                                                       float* __restrict__ Xn,
                                                       const uint32_t* __restrict__ npwh,
                                                       const uint32_t* __restrict__ npwl,
                                                       const float* __restrict__ npb,
                                                       int has_pre) {
    extern __shared__ char smem[];
    float* s_bp  = (float*)(smem + 0);
    float* s_bl  = (float*)(smem + 256);
    float* s_amp = (float*)(smem + 512);
    float* s_att = (float*)(smem + 1024);
    float* s_pb  = (float*)(smem + 1536);
    uint32_t* sAh = (uint32_t*)(smem + 2048);
    uint32_t* sAl = (uint32_t*)(smem + 20480);
    uint32_t* sBh = (uint32_t*)(smem + 38912);   // phase1: 3 mats stride 2304 u32
    uint32_t* sBl = (uint32_t*)(smem + 66560);   // phase1/2: 1 mat

    int tid = threadIdx.x;
    int lane = tid & 31, wid = tid >> 5;
    int gid = lane >> 2, tq = lane & 3;
    int mrow = wid * 16;
    int row0 = blockIdx.x * 128;

    if (tid < 64) {
        s_bp[tid] = bp[tid];
        s_bl[tid] = bl[tid];
        if (has_pre) s_pb[tid] = npb[tid];
    }
    if (tid < 128) {
        int gr = row0 + tid;
        s_amp[tid] = (gr < NN) ? d_amp[gr] : 0.f;
        s_att[tid] = (gr < NN) ? d_att[gr] : 0.f;
    }

    float c1[8][4], c2[8][4], c3[8][4];
    #pragma unroll
    for (int nt = 0; nt < 8; nt++)
        #pragma unroll
        for (int q = 0; q < 4; q++) { c1[nt][q] = 0.f; c2[nt][q] = 0.f; c3[nt][q] = 0.f; }

    int rr = tid >> 3, f = tid & 7;

    // ---------- phase 1: 10 A-chunks (2 x, 8 aggr) ----------
    for (int ch = 0; ch < 10; ch++) {
        __syncthreads();
        bool isX = (ch < 2);
        #pragma unroll
        for (int it = 0; it < 4; it++) {
            int r = rr + it * 32;
            int gr = row0 + r;
            float4 v = make_float4(0.f, 0.f, 0.f, 0.f);
            if (gr < NN) {
                if (isX) v = *(const float4*)(X + (size_t)gr * 64 + ch * 32 + f * 4);
                else     v = *(const float4*)(d_aggr + (size_t)gr * 256 + (ch - 2) * 32 + f * 4);
            }
            uint32_t h0, l0, h1, l1, h2, l2, h3, l3;
            tf32_split(v.x, h0, l0); tf32_split(v.y, h1, l1);
            tf32_split(v.z, h2, l2); tf32_split(v.w, h3, l3);
            int base = r * 36 + f * 4;
            *(uint4*)&sAh[base] = make_uint4(h0, h1, h2, h3);
            *(uint4*)&sAl[base] = make_uint4(l0, l1, l2, l3);
        }
        if (isX) {
            #pragma unroll
            for (int i = 0; i < 2; i++) {
                int idx = tid + i * 256;
                int j = idx >> 3, fb = idx & 7;
                int src = j * 832 + ch * 32 + fb * 4;
                *(uint4*)&sBh[j * 36 + fb * 4] = *(const uint4*)(wph + src);
                *(uint4*)&sBl[j * 36 + fb * 4] = *(const uint4*)(wpl + src);
            }
        } else {
            int ca = ch - 2;
            #pragma unroll
            for (int i = 0; i < 2; i++) {
                int idx = tid + i * 256;
                int j = idx >> 3, fb = idx & 7;
                int src = j * 832 + 64 + ca * 32 + fb * 4;
                *(uint4*)&sBh[j * 36 + fb * 4] = *(const uint4*)(wph + src);
                *(uint4*)&sBl[j * 36 + fb * 4] = *(const uint4*)(wpl + src);
            }
            #pragma unroll
            for (int m = 1; m < 3; m++) {
                int koff = 64 + m * 256 + ca * 32;
                #pragma unroll
                for (int i = 0; i < 2; i++) {
                    int idx = tid + i * 256;
                    int j = idx >> 3, fb = idx & 7;
                    int src = j * 832 + koff + fb * 4;
                    *(uint4*)&sBh[m * 2304 + j * 36 + fb * 4] = *(const uint4*)(wph + src);
                }
            }
        }
        __syncthreads();
        #pragma unroll
        for (int ks = 0; ks < 4; ks++) {
            int k0 = ks * 8;
            int ra = (mrow + gid) * 36 + k0 + tq;
            int rb = (mrow + gid + 8) * 36 + k0 + tq;
            uint32_t ah0 = sAh[ra], ah1 = sAh[rb], ah2 = sAh[ra + 4], ah3 = sAh[rb + 4];
            uint32_t al0 = sAl[ra], al1 = sAl[rb], al2 = sAl[ra + 4], al3 = sAl[rb + 4];
            if (isX) {
                #pragma unroll
                for (int nt = 0; nt < 8; nt++) {
                    int nb = (nt * 8 + gid) * 36 + k0 + tq;
                    uint32_t bh0 = sBh[nb], bh1 = sBh[nb + 4];
                    uint32_t bl0 = sBl[nb], bl1 = sBl[nb + 4];
                    MMA3(c1[nt], ah0, ah1, ah2, ah3, al0, al1, al2, al3, bh0, bh1, bl0, bl1);
                }
            } else {
                #pragma unroll
                for (int nt = 0; nt < 8; nt++) {
                    int nb = (nt * 8 + gid) * 36 + k0 + tq;
                    uint32_t bh0 = sBh[nb], bh1 = sBh[nb + 4];
                    uint32_t bl0 = sBl[nb], bl1 = sBl[nb + 4];
                    MMA3(c1[nt], ah0, ah1, ah2, ah3, al0, al1, al2, al3, bh0, bh1, bl0, bl1);
                    mma_tf32(c2[nt][0], c2[nt][1], c2[nt][2], c2[nt][3],
                             ah0, ah1, ah2, ah3, sBh[nb + 2304], sBh[nb + 2304 + 4]);
                    mma_tf32(c3[nt][0], c3[nt][1], c3[nt][2], c3[nt][3],
                             ah0, ah1, ah2, ah3, sBh[nb + 4608], sBh[nb + 4608 + 4]);
                }
            }
        }
    }

    // combine in-place into c1: c1 + amp*c2 + att*c3 + bp
    {
        float a0 = s_amp[mrow + gid], t0 = s_att[mrow + gid];
        float a1 = s_amp[mrow + gid + 8], t1 = s_att[mrow + gid + 8];
        #pragma unroll
        for (int nt = 0; nt < 8; nt++) {
            int col = nt * 8 + 2 * tq;
            c1[nt][0] += a0 * c2[nt][0] + t0 * c3[nt][0] + s_bp[col];
            c1[nt][1] += a0 * c2[nt][1] + t0 * c3[nt][1] + s_bp[col + 1];
            c1[nt][2] += a1 * c2[nt][2] + t1 * c3[nt][2] + s_bp[col];
            c1[nt][3] += a1 * c2[nt][3] + t1 * c3[nt][3] + s_bp[col + 1];
        }
    }

    // ---------- phase 2: lin GEMM (3xTF32), K=64 in 2 chunks of 32 ----------
    #pragma unroll
    for (int nt = 0; nt < 8; nt++)
        #pragma unroll
        for (int q = 0; q < 4; q++) c3[nt][q] = 0.f;

    for (int ch2 = 0; ch2 < 2; ch2++) {
        __syncthreads();
        #pragma unroll
        for (int nt2 = 0; nt2 < 4; nt2++) {
            int nt = ch2 * 4 + nt2;
            int col = nt * 8 + 2 * tq;
            int lc = col - ch2 * 32;
            int r0 = (mrow + gid) * 36, r1 = (mrow + gid + 8) * 36;
            uint32_t h, l;
            tf32_split(c1[nt][0], h, l); sAh[r0 + lc]     = h; sAl[r0 + lc]     = l;
            tf32_split(c1[nt][1], h, l); sAh[r0 + lc + 1] = h; sAl[r0 + lc + 1] = l;
            tf32_split(c1[nt][2], h, l); sAh[r1 + lc]     = h; sAl[r1 + lc]     = l;
            tf32_split(c1[nt][3], h, l); sAh[r1 + lc + 1] = h; sAl[r1 + lc + 1] = l;
        }
        #pragma unroll
        for (int i = 0; i < 2; i++) {
            int idx = tid + i * 256;
            int j = idx >> 3, fb = idx & 7;
            int src = j * 64 + ch2 * 32 + fb * 4;
            *(uint4*)&sBh[j * 36 + fb * 4] = *(const uint4*)(lwh + src);
            *(uint4*)&sBl[j * 36 + fb * 4] = *(const uint4*)(lwl + src);
        }
        __syncthreads();
        #pragma unroll
        for (int ks = 0; ks < 4; ks++) {
            int k0 = ks * 8;
            int ra = (mrow + gid) * 36 + k0 + tq;
            int rb = (mrow + gid + 8) * 36 + k0 + tq;
            uint32_t ah0 = sAh[ra], ah1 = sAh[rb], ah2 = sAh[ra + 4], ah3 = sAh[rb + 4];
            uint32_t al0 = sAl[ra], al1 = sAl[rb], al2 = sAl[ra + 4], al3 = sAl[rb + 4];
            #pragma unroll
            for (int nt = 0; nt < 8; nt++) {
                int nb = (nt * 8 + gid) * 36 + k0 + tq;
                uint32_t bh0 = sBh[nb], bh1 = sBh[nb + 4];
                uint32_t bl0 = sBl[nb], bl1 = sBl[nb + 4];
                MMA3(c3[nt], ah0, ah1, ah2, ah3, al0, al1, al2, al3, bh0, bh1, bl0, bl1);
            }
        }
    }

    // epilogue: o = relu(c3 + bl) -> gmem (and keep for fused pre)
    int grow0 = row0 + mrow + gid;
    int grow1 = grow0 + 8;
    float o[8][4];
    #pragma unroll
    for (int nt = 0; nt < 8; nt++) {
        int col = nt * 8 + 2 * tq;
        float bl0 = s_bl[col], bl1 = s_bl[col + 1];
        o[nt][0] = fmaxf(c3[nt][0] + bl0, 0.f);
        o[nt][1] = fmaxf(c3[nt][1] + bl1, 0.f);
        o[nt][2] = fmaxf(c3[nt][2] + bl0, 0.f);
        o[nt][3] = fmaxf(c3[nt][3] + bl1, 0.f);
        if (grow0 < NN)
            *(float2*)(Xn + (size_t)grow0 * 64 + col) = make_float2(o[nt][0], o[nt][1]);
        if (grow1 < NN)
            *(float2*)(Xn + (size_t)grow1 * 64 + col) = make_float2(o[nt][2], o[nt][3]);
    }

    if (!has_pre) return;

    // ---------- phase 3: fused next-layer pre GEMM: zb = [o@A+b | o@B] ----------
    // reuse c1 (nt 0..7) and c2 (nt 8..15) as zb accumulators
    uint32_t* sB = sBh;   // contiguous 9216 u32: Bh [0,4608), Bl [4608,9216)
    #pragma unroll
    for (int nt = 0; nt < 8; nt++)
        #pragma unroll
        for (int q = 0; q < 4; q++) { c1[nt][q] = 0.f; c2[nt][q] = 0.f; }

    for (int ch3 = 0; ch3 < 2; ch3++) {
        __syncthreads();
        #pragma unroll
        for (int nt2 = 0; nt2 < 4; nt2++) {
            int nt = ch3 * 4 + nt2;
            int col = nt * 8 + 2 * tq;
            int lc = col - ch3 * 32;
            int r0 = (mrow + gid) * 36, r1 = (mrow + gid + 8) * 36;
            uint32_t h, l;
            tf32_split(o[nt][0], h, l); sAh[r0 + lc]     = h; sAl[r0 + lc]     = l;
            tf32_split(o[nt][1], h, l); sAh[r0 + lc + 1] = h; sAl[r0 + lc + 1] = l;
            tf32_split(o[nt][2], h, l); sAh[r1 + lc]     = h; sAl[r1 + lc]     = l;
            tf32_split(o[nt][3], h, l); sAh[r1 + lc + 1] = h; sAl[r1 + lc + 1] = l;
        }
        #pragma unroll
        for (int i = 0; i < 4; i++) {
            int idx = tid + i * 256;       // 0..1023 -> 128 rows x 8 uint4
            int j = idx >> 3, fb = idx & 7;
            int src = j * 64 + ch3 * 32 + fb * 4;
            *(uint4*)&sB[j * 36 + fb * 4]        = *(const uint4*)(npwh + src);
            *(uint4*)&sB[4608 + j * 36 + fb * 4] = *(const uint4*)(npwl + src);
        }
        __syncthreads();
        #pragma unroll
        for (int ks = 0; ks < 4; ks++) {
            int k0 = ks * 8;
            int ra = (mrow + gid) * 36 + k0 + tq;
            int rb = (mrow + gid + 8) * 36 + k0 + tq;
            uint32_t ah0 = sAh[ra], ah1 = sAh[rb], ah2 = sAh[ra + 4], ah3 = sAh[rb + 4];
            uint32_t al0 = sAl[ra], al1 = sAl[rb], al2 = sAl[ra + 4], al3 = sAl[rb + 4];
            #pragma unroll
            for (int nt = 0; nt < 16; nt++) {
                int nb = (nt * 8 + gid) * 36 + k0 + tq;
                uint32_t bh0 = sB[nb], bh1 = sB[nb + 4];
                uint32_t bl0 = sB[4608 + nb], bl1 = sB[4608 + nb + 4];
                if (nt < 8) {
                    MMA3(c1[nt], ah0, ah1, ah2, ah3, al0, al1, al2, al3, bh0, bh1, bl0, bl1);
                } else {
                    MMA3(c2[nt - 8], ah0, ah1, ah2, ah3, al0, al1, al2, al3, bh0, bh1, bl0, bl1);
                }
            }
        }
    }
    // write zb: cols<64 get +bias (base part), cols>=64 raw (z part)
    #pragma unroll
    for (int nt = 0; nt < 16; nt++) {
        int col = nt * 8 + 2 * tq;
        float b0 = (col < 64) ? s_pb[col] : 0.f;
        float b1 = (col < 64) ? s_pb[col + 1] : 0.f;
        const float* C = (nt < 8) ? c1[nt] : c2[nt - 8];
        if (grow0 < NN)
            *(float2*)(d_zb + (size_t)grow0 * 128 + col) = make_float2(C[0] + b0, C[1] + b1);
        if (grow1 < NN)
            *(float2*)(d_zb + (size_t)grow1 * 128 + col) = make_float2(C[2] + b0, C[3] + b1);
    }
}

// ---------------- pooling + MLP ----------------
__global__ void k_pool(const float* __restrict__ X, const int* __restrict__ batch) {
    int idx = blockIdx.x * blockDim.x + threadIdx.x;
    int f = idx & 63;
    int chunk = idx >> 6;
    int n0 = chunk * 8;
    if (n0 >= NN) return;
    int ne = n0 + 8 < NN ? n0 + 8 : NN;
    int cg = batch[n0];
    float acc = 0.f;
    int cnt = 0;
    for (int n = n0; n < ne; n++) {
        int g = batch[n];
        if (g != cg) {
            atomicAdd(&d_pool[cg * 64 + f], acc);
            if (f == 0) atomicAdd(&d_cnt[cg], cnt);
            acc = 0.f; cnt = 0; cg = g;
        }
        acc += X[(size_t)n * 64 + f];
        cnt++;
    }
    atomicAdd(&d_pool[cg * 64 + f], acc);
    if (f == 0) atomicAdd(&d_cnt[cg], cnt);
}

__global__ void k_mlp(const float* __restrict__ W1, const float* __restrict__ b1,
                      const float* __restrict__ W2, const float* __restrict__ b2,
                      float* __restrict__ out) {
    __shared__ float gv[64], hv[64];
    int g = blockIdx.x, t = threadIdx.x;
    int c = d_cnt[g];
    float cntf = (float)(c > 1 ? c : 1);
    gv[t] = d_pool[g * 64 + t] / cntf;
    __syncthreads();
    float a = b1[t];
    #pragma unroll 8
    for (int k = 0; k < 64; k++) a += W1[t * 64 + k] * gv[k];
    hv[t] = fmaxf(a, 0.f);
    __syncthreads();
    if (t < 16) {
        float o = b2[t];
        #pragma unroll 8
        for (int k = 0; k < 64; k++) o += W2[t * 64 + k] * hv[k];
        out[g * 16 + t] = o;
    }
}

// ---------------- launch ----------------
extern "C" void kernel_launch(void* const* d_in, const int* in_sizes, int n_in,
                              void* d_out, int out_size) {
    const float* x      = (const float*)d_in[0];
    const int*   ei     = (const int*)d_in[1];
    const int*   batch  = (const int*)d_in[2];
    const float* pre_w  = (const float*)d_in[3];
    const float* pre_b  = (const float*)d_in[4];
    const float* post_w = (const float*)d_in[5];
    const float* post_b = (const float*)d_in[6];
    const float* lin_w  = (const float*)d_in[7];
    const float* lin_b  = (const float*)d_in[8];
    const float* mw1    = (const float*)d_in[9];
    const float* mb1    = (const float*)d_in[10];
    const float* mw2    = (const float*)d_in[11];
    const float* mb2    = (const float*)d_in[12];
    float* out = (float*)d_out;
    const int* srcp = ei;
    const int* dstp = ei + NE;

    void *pa, *pb, *pw;
    cudaGetSymbolAddress(&pa, d_xa);
    cudaGetSymbolAddress(&pb, d_xb);
    float* xa = (float*)pa;
    float* xb = (float*)pb;
    uint32_t *wph, *wpl, *pwh, *pwl, *lwh, *lwl;
    cudaGetSymbolAddress(&pw, d_wph); wph = (uint32_t*)pw;
    cudaGetSymbolAddress(&pw, d_wpl); wpl = (uint32_t*)pw;
    cudaGetSymbolAddress(&pw, d_pwh); pwh = (uint32_t*)pw;
    cudaGetSymbolAddress(&pw, d_pwl); pwl = (uint32_t*)pw;
    cudaGetSymbolAddress(&pw, d_lwh); lwh = (uint32_t*)pw;
    cudaGetSymbolAddress(&pw, d_lwl); lwl = (uint32_t*)pw;

    cudaFuncSetAttribute(k_post_mma_sync, cudaFuncAttributeMaxDynamicSharedMemorySize, POST_SMEM);
    cudaFuncSetAttribute(k_pre_mma, cudaFuncAttributeMaxDynamicSharedMemorySize, PRE_SMEM);

    k_init<<<(NN + 255) / 256, 256>>>();
    k_splitw<<<312, 256>>>(pre_w, post_w, lin_w);
    k_degree<<<(NE + 255) / 256, 256>>>(dstp);
    k_scan1<<<NB_SCAN, 256>>>();
    k_scan3<<<NB_SCAN, 256>>>();
    k_fill<<<(NE + 255) / 256, 256>>>(srcp, dstp);

    // layer 0 pre (reads input x)
    k_pre_mma<<<(NN + 127) / 128, 256, PRE_SMEM>>>(x, pwh, pwl, pre_b);

    const float* cur = x;
    float* nxt = xa;
    for (int l = 0; l < 3; l++) {
        int has_pre = (l < 2) ? 1 : 0;
        int nl = (l + 1 < 3) ? (l + 1) : 0;   // dummy valid ptr when !has_pre
        k_aggr<<<(NN * 32 + 255) / 256, 256>>>();
        k_post_mma_sync<<<(NN + 127) / 128, 256, POST_SMEM>>>(
            cur, wph + l * 53248, wpl + l * 53248, post_b + l * 64,
            lwh + l * 4096, lwl + l * 4096, lin_b + l * 64, nxt,
            pwh + nl * 8192, pwl + nl * 8192, pre_b + nl * 64, has_pre);
        cur = nxt;
        nxt = (nxt == xa) ? xb : xa;
    }
    k_pool<<<(((NN + 7) / 8) * 64 + 255) / 256, 256>>>(cur, batch);
    k_mlp<<<NG, 64>>>(mw1, mb1, mw2, mb2, out);
}

// round 17
// speedup vs baseline: 1.0572x; 1.0572x over previous
#include <cuda_runtime.h>
#include <cstdint>
#include <math.h>

#define NN 50000
#define NE 800000
#define NG 64
#define NB_SCAN 196   // ceil(NN/256)

// ---------------- scratch (static __device__, no allocs) ----------------
__device__ __align__(16) float d_zb[NN * 128];    // [base(64) | z(64)] per node
__device__ __align__(16) float d_aggr[NN * 256];  // [mean|min|max|std]
__device__ __align__(16) float d_xa[NN * 64];
__device__ __align__(16) float d_xb[NN * 64];
__device__ int   d_deg[NN];
__device__ int   d_off[NN + 1];
__device__ int   d_cur[NN];
__device__ int   d_csr[NE];
__device__ float d_amp[NN];
__device__ float d_att[NN];
__device__ float d_pool[NG * 64];
__device__ int   d_cnt[NG];
__device__ int   d_part[NB_SCAN];
__device__ float d_logpart[NB_SCAN];
// presplit tf32 hi/lo weights
__device__ __align__(16) uint32_t d_wph[3 * 64 * 832];
__device__ __align__(16) uint32_t d_wpl[3 * 64 * 832];
__device__ __align__(16) uint32_t d_pwh[3 * 128 * 64];
__device__ __align__(16) uint32_t d_pwl[3 * 128 * 64];
__device__ __align__(16) uint32_t d_lwh[3 * 64 * 64];
__device__ __align__(16) uint32_t d_lwl[3 * 64 * 64];

// ---------------- mma.sync tf32 helpers (sm_80+ baseline PTX) ----------
__device__ __forceinline__ uint32_t f2tf(float x) {
    uint32_t u;
    asm("cvt.rna.tf32.f32 %0, %1;" : "=r"(u) : "f"(x));
    return u;
}

// RNA split: v = hi + lo, hi round-to-nearest tf32 (unbiased)
__device__ __forceinline__ void tf32_split(float v, uint32_t& hi, uint32_t& lo) {
    uint32_t h = f2tf(v);
    hi = h;
    lo = f2tf(v - __uint_as_float(h));
}

__device__ __forceinline__ void mma_tf32(float& c0, float& c1, float& c2, float& c3,
                                         uint32_t a0, uint32_t a1, uint32_t a2, uint32_t a3,
                                         uint32_t b0, uint32_t b1) {
    asm volatile("mma.sync.aligned.m16n8k8.row.col.f32.tf32.tf32.f32 "
        "{%0,%1,%2,%3}, {%4,%5,%6,%7}, {%8,%9}, {%0,%1,%2,%3};"
        : "+f"(c0), "+f"(c1), "+f"(c2), "+f"(c3)
        : "r"(a0), "r"(a1), "r"(a2), "r"(a3), "r"(b0), "r"(b1));
}

// 3-term 3xTF32 accumulate
#define MMA3(C, ah0, ah1, ah2, ah3, al0, al1, al2, al3, bh0, bh1, bl0, bl1) do { \
    mma_tf32(C[0], C[1], C[2], C[3], ah0, ah1, ah2, ah3, bh0, bh1); \
    mma_tf32(C[0], C[1], C[2], C[3], ah0, ah1, ah2, ah3, bl0, bl1); \
    mma_tf32(C[0], C[1], C[2], C[3], al0, al1, al2, al3, bh0, bh1); \
} while (0)

// ---------------- setup kernels ----------------
__global__ void k_init() {
    int i = blockIdx.x * blockDim.x + threadIdx.x;
    if (i < NN) d_deg[i] = 0;
    if (i < NG * 64) d_pool[i] = 0.f;
    if (i < NG) d_cnt[i] = 0;
}

__global__ void k_degree(const int* __restrict__ dst) {
    int e = blockIdx.x * blockDim.x + threadIdx.x;
    if (e < NE) atomicAdd(&d_deg[dst[e]], 1);
}

// split all weights into tf32 hi/lo once
__global__ void k_splitw(const float* __restrict__ pre_w,
                         const float* __restrict__ post_w,
                         const float* __restrict__ lin_w) {
    int stride = gridDim.x * blockDim.x;
    int i0 = blockIdx.x * blockDim.x + threadIdx.x;
    for (int t = i0; t < 3 * 64 * 832; t += stride) {
        uint32_t h, l;
        tf32_split(post_w[t], h, l);
        d_wph[t] = h; d_wpl[t] = l;
    }
    for (int t = i0; t < 3 * 128 * 64; t += stride) {
        int l = t >> 13, r = t & 8191;
        int j = r >> 6, k = r & 63;
        int jj = j & 63, off = (j >= 64) ? 64 : 0;
        float v = pre_w[l * 8192 + jj * 128 + off + k];
        uint32_t h, lo;
        tf32_split(v, h, lo);
        d_pwh[t] = h; d_pwl[t] = lo;
    }
    for (int t = i0; t < 3 * 64 * 64; t += stride) {
        uint32_t h, l;
        tf32_split(lin_w[t], h, l);
        d_lwh[t] = h; d_lwl[t] = l;
    }
}

// per-block sums of degree + log-degree
__global__ void k_scan1() {
    __shared__ int ssum[8];
    __shared__ float slog[8];
    int tid = threadIdx.x, lane = tid & 31, w = tid >> 5;
    int i = blockIdx.x * 256 + tid;
    int v = (i < NN) ? d_deg[i] : 0;
    float l = (i < NN) ? logf((float)v + 1.f) : 0.f;
    int s = v;
    #pragma unroll
    for (int d = 16; d; d >>= 1) {
        s += __shfl_xor_sync(0xffffffffu, s, d);
        l += __shfl_xor_sync(0xffffffffu, l, d);
    }
    if (lane == 0) { ssum[w] = s; slog[w] = l; }
    __syncthreads();
    if (tid == 0) {
        int t = 0; float lt = 0.f;
        #pragma unroll
        for (int k = 0; k < 8; k++) { t += ssum[k]; lt += slog[k]; }
        d_part[blockIdx.x] = t;
        d_logpart[blockIdx.x] = lt;
    }
}

// per-element offsets + amp/att scalars; block prefix + avglog computed redundantly
__global__ void k_scan3() {
    __shared__ int ws[8];
    __shared__ int s_boff;
    __shared__ float s_avg;
    int tid = threadIdx.x, lane = tid & 31, w = tid >> 5;
    int bid = blockIdx.x;
    if (w == 0) {
        int acc = 0;
        for (int k = lane; k < bid; k += 32) acc += d_part[k];
        #pragma unroll
        for (int d = 16; d; d >>= 1) acc += __shfl_xor_sync(0xffffffffu, acc, d);
        if (lane == 0) s_boff = acc;
    }
    if (w == 1 && lane == 0) {
        float s = 0.f;
        for (int k = 0; k < NB_SCAN; k++) s += d_logpart[k];
        s_avg = s / (float)NN;
    }
    int i = bid * 256 + tid;
    int v = (i < NN) ? d_deg[i] : 0;
    int x = v;
    #pragma unroll
    for (int d = 1; d < 32; d <<= 1) {
        int t = __shfl_up_sync(0xffffffffu, x, d);
        if (lane >= d) x += t;
    }
    if (lane == 31) ws[w] = x;
    __syncthreads();
    if (tid == 0) {
        int acc = 0;
        #pragma unroll
        for (int k = 0; k < 8; k++) { int t = ws[k]; ws[k] = acc; acc += t; }
    }
    __syncthreads();
    int excl = s_boff + ws[w] + x - v;
    if (i < NN) {
        d_off[i] = excl;
        d_cur[i] = excl;
        float avg = s_avg;
        float degf = (float)(v > 1 ? v : 1);
        float ld = logf(degf + 1.f);
        d_amp[i] = ld / avg;
        d_att[i] = avg / ld;
    }
    if (i == 0) d_off[NN] = NE;
}

__global__ void k_fill(const int* __restrict__ src, const int* __restrict__ dst) {
    int e = blockIdx.x * blockDim.x + threadIdx.x;
    if (e < NE) {
        int dn = dst[e];
        int p = atomicAdd(&d_cur[dn], 1);
        d_csr[p] = src[e];
    }
}

// ---------------- pre GEMM via 3xTF32 mma: [128 rows] x [64 -> 128] ----------
// smem: [0,256) bias | [2048,20480) Ah 128x36 | [20480,38912) Al
//       [38912,57344) Bh 128x36 | [57344,75776) Bl
#define PRE_SMEM 75776

__global__ __launch_bounds__(256) void k_pre_mma(const float* __restrict__ X,
                                                 const uint32_t* __restrict__ pwh,
                                                 const uint32_t* __restrict__ pwl,
                                                 const float* __restrict__ B) {
    extern __shared__ char smem[];
    float* s_bias = (float*)(smem + 0);
    uint32_t* sAh = (uint32_t*)(smem + 2048);
    uint32_t* sAl = (uint32_t*)(smem + 20480);
    uint32_t* sBh = (uint32_t*)(smem + 38912);
    uint32_t* sBl = (uint32_t*)(smem + 57344);

    int tid = threadIdx.x;
    int lane = tid & 31, wid = tid >> 5;
    int gid = lane >> 2, tq = lane & 3;
    int mrow = wid * 16;
    int row0 = blockIdx.x * 128;
    if (tid < 64) s_bias[tid] = B[tid];

    float c[16][4];
    #pragma unroll
    for (int nt = 0; nt < 16; nt++)
        #pragma unroll
        for (int q = 0; q < 4; q++) c[nt][q] = 0.f;

    int rr = tid >> 3, f = tid & 7;

    for (int ch = 0; ch < 2; ch++) {
        __syncthreads();
        #pragma unroll
        for (int it = 0; it < 4; it++) {
            int r = rr + it * 32;
            int gr = row0 + r;
            float4 v = make_float4(0.f, 0.f, 0.f, 0.f);
            if (gr < NN) v = *(const float4*)(X + (size_t)gr * 64 + ch * 32 + f * 4);
            uint32_t h0, l0, h1, l1, h2, l2, h3, l3;
            tf32_split(v.x, h0, l0); tf32_split(v.y, h1, l1);
            tf32_split(v.z, h2, l2); tf32_split(v.w, h3, l3);
            int base = r * 36 + f * 4;
            *(uint4*)&sAh[base] = make_uint4(h0, h1, h2, h3);
            *(uint4*)&sAl[base] = make_uint4(l0, l1, l2, l3);
        }
        #pragma unroll
        for (int it = 0; it < 4; it++) {
            int idx = tid + it * 256;
            int j = idx >> 3, fb = idx & 7;
            int src = j * 64 + ch * 32 + fb * 4;
            uint4 h = *(const uint4*)(pwh + src);
            uint4 l = *(const uint4*)(pwl + src);
            int dst = j * 36 + fb * 4;
            *(uint4*)&sBh[dst] = h;
            *(uint4*)&sBl[dst] = l;
        }
        __syncthreads();
        #pragma unroll
        for (int ks = 0; ks < 4; ks++) {
            int k0 = ks * 8;
            int ra = (mrow + gid) * 36 + k0 + tq;
            int rb = (mrow + gid + 8) * 36 + k0 + tq;
            uint32_t ah0 = sAh[ra], ah1 = sAh[rb], ah2 = sAh[ra + 4], ah3 = sAh[rb + 4];
            uint32_t al0 = sAl[ra], al1 = sAl[rb], al2 = sAl[ra + 4], al3 = sAl[rb + 4];
            #pragma unroll
            for (int nt = 0; nt < 16; nt++) {
                int nb = (nt * 8 + gid) * 36 + k0 + tq;
                uint32_t bh0 = sBh[nb], bh1 = sBh[nb + 4];
                uint32_t bl0 = sBl[nb], bl1 = sBl[nb + 4];
                MMA3(c[nt], ah0, ah1, ah2, ah3, al0, al1, al2, al3, bh0, bh1, bl0, bl1);
            }
        }
    }
    int grow0 = row0 + mrow + gid;
    int grow1 = grow0 + 8;
    #pragma unroll
    for (int nt = 0; nt < 16; nt++) {
        int col = nt * 8 + 2 * tq;
        float b0 = (col < 64) ? s_bias[col] : 0.f;
        float b1 = (col < 64) ? s_bias[col + 1] : 0.f;
        if (grow0 < NN)
            *(float2*)(d_zb + (size_t)grow0 * 128 + col) = make_float2(c[nt][0] + b0, c[nt][1] + b1);
        if (grow1 < NN)
            *(float2*)(d_zb + (size_t)grow1 * 128 + col) = make_float2(c[nt][2] + b0, c[nt][3] + b1);
    }
}

// ---------------- aggregation: 1 warp per node, 8-way, z-only stats ----------
__global__ __launch_bounds__(256) void k_aggr() {
    int gw = (blockIdx.x * blockDim.x + threadIdx.x) >> 5;
    int lane = threadIdx.x & 31;
    if (gw >= NN) return;
    int beg = d_off[gw], end = d_off[gw + 1];
    float2 base = *(const float2*)(d_zb + (size_t)gw * 128 + lane * 2);
    float s1x = 0.f, s1y = 0.f, s2x = 0.f, s2y = 0.f;
    float mnx = INFINITY, mny = INFINITY, mxx = -INFINITY, mxy = -INFINITY;
    int e = beg;
    for (; e + 8 <= end; e += 8) {
        int idx[8];
        #pragma unroll
        for (int u = 0; u < 8; u++) idx[u] = d_csr[e + u];
        float2 z[8];
        #pragma unroll
        for (int u = 0; u < 8; u++)
            z[u] = *(const float2*)(d_zb + (size_t)idx[u] * 128 + 64 + lane * 2);
        #pragma unroll
        for (int u = 0; u < 8; u++) {
            s1x += z[u].x; s2x += z[u].x * z[u].x;
            mnx = fminf(mnx, z[u].x); mxx = fmaxf(mxx, z[u].x);
            s1y += z[u].y; s2y += z[u].y * z[u].y;
            mny = fminf(mny, z[u].y); mxy = fmaxf(mxy, z[u].y);
        }
    }
    for (; e < end; e++) {
        int s = d_csr[e];
        float2 z = *(const float2*)(d_zb + (size_t)s * 128 + 64 + lane * 2);
        s1x += z.x; s2x += z.x * z.x; mnx = fminf(mnx, z.x); mxx = fmaxf(mxx, z.x);
        s1y += z.y; s2y += z.y * z.y; mny = fminf(mny, z.y); mxy = fmaxf(mxy, z.y);
    }
    int drI = end - beg;
    float* a = d_aggr + (size_t)gw * 256;
    if (drI == 0) {
        float sv = sqrtf(1e-5f);
        *(float2*)(a + lane * 2)       = make_float2(0.f, 0.f);
        *(float2*)(a + 64 + lane * 2)  = make_float2(0.f, 0.f);
        *(float2*)(a + 128 + lane * 2) = make_float2(0.f, 0.f);
        *(float2*)(a + 192 + lane * 2) = make_float2(sv, sv);
        return;
    }
    float deg = (float)drI;
    float mzx = s1x / deg, mzy = s1y / deg;
    float meanx = base.x + mzx, meany = base.y + mzy;
    float stdx = sqrtf(fmaxf(s2x / deg - mzx * mzx, 0.f) + 1e-5f);
    float stdy = sqrtf(fmaxf(s2y / deg - mzy * mzy, 0.f) + 1e-5f);
    *(float2*)(a + lane * 2)       = make_float2(meanx, meany);
    *(float2*)(a + 64 + lane * 2)  = make_float2(base.x + mnx, base.y + mny);
    *(float2*)(a + 128 + lane * 2) = make_float2(base.x + mxx, base.y + mxy);
    *(float2*)(a + 192 + lane * 2) = make_float2(stdx, stdy);
}

// ---------------- post+lin via 3xTF32 mma, mixed precision ----------
// c1 aggr path 3xTF32; x path + c2/c3 single-pass tf32; lin 3xTF32.
// smem: [0,256) bp | [256,512) bl | [512,1024) amp | [1024,1536) att
//  [2048,20480) Ah 128x36 | [20480,38912) Al
//  [38912,66560) Bh 3x64x36 | [66560,75776) Bl 1x64x36
#define POST_SMEM 75776

__global__ __launch_bounds__(256) void k_post_mma_sync(const float* __restrict__ X,
                                                       const uint32_t* __restrict__ wph,
                                                       const uint32_t* __restrict__ wpl,
                                                       const float* __restrict__ bp,
                                                       const uint32_t* __restrict__ lwh,
                                                       const uint32_t* __restrict__ lwl,
                                                       const float* __restrict__ bl,
                                                       float* __restrict__ Xn) {
    extern __shared__ char smem[];
    float* s_bp  = (float*)(smem + 0);
    float* s_bl  = (float*)(smem + 256);
    float* s_amp = (float*)(smem + 512);
    float* s_att = (float*)(smem + 1024);
    uint32_t* sAh = (uint32_t*)(smem + 2048);
    uint32_t* sAl = (uint32_t*)(smem + 20480);
    uint32_t* sBh = (uint32_t*)(smem + 38912);   // 3 mats, stride 2304 u32
    uint32_t* sBl = (uint32_t*)(smem + 66560);   // 1 mat

    int tid = threadIdx.x;
    int lane = tid & 31, wid = tid >> 5;
    int gid = lane >> 2, tq = lane & 3;
    int mrow = wid * 16;
    int row0 = blockIdx.x * 128;

    if (tid < 64) { s_bp[tid] = bp[tid]; s_bl[tid] = bl[tid]; }
    if (tid < 128) {
        int gr = row0 + tid;
        s_amp[tid] = (gr < NN) ? d_amp[gr] : 0.f;
        s_att[tid] = (gr < NN) ? d_att[gr] : 0.f;
    }

    float c1[8][4], c2[8][4], c3[8][4];
    #pragma unroll
    for (int nt = 0; nt < 8; nt++)
        #pragma unroll
        for (int q = 0; q < 4; q++) { c1[nt][q] = 0.f; c2[nt][q] = 0.f; c3[nt][q] = 0.f; }

    int rr = tid >> 3, f = tid & 7;

    // ---------- phase 1: 10 A-chunks (2 x [single-pass], 8 aggr [mixed]) ----------
    for (int ch = 0; ch < 10; ch++) {
        __syncthreads();
        bool isX = (ch < 2);
        #pragma unroll
        for (int it = 0; it < 4; it++) {
            int r = rr + it * 32;
            int gr = row0 + r;
            float4 v = make_float4(0.f, 0.f, 0.f, 0.f);
            if (gr < NN) {
                if (isX) v = *(const float4*)(X + (size_t)gr * 64 + ch * 32 + f * 4);
                else     v = *(const float4*)(d_aggr + (size_t)gr * 256 + (ch - 2) * 32 + f * 4);
            }
            uint32_t h0, l0, h1, l1, h2, l2, h3, l3;
            tf32_split(v.x, h0, l0); tf32_split(v.y, h1, l1);
            tf32_split(v.z, h2, l2); tf32_split(v.w, h3, l3);
            int base = r * 36 + f * 4;
            *(uint4*)&sAh[base] = make_uint4(h0, h1, h2, h3);
            *(uint4*)&sAl[base] = make_uint4(l0, l1, l2, l3);
        }
        if (isX) {
            // x path single-pass: stage Bh only
            #pragma unroll
            for (int i = 0; i < 2; i++) {
                int idx = tid + i * 256;
                int j = idx >> 3, fb = idx & 7;
                int src = j * 832 + ch * 32 + fb * 4;
                *(uint4*)&sBh[j * 36 + fb * 4] = *(const uint4*)(wph + src);
            }
        } else {
            int ca = ch - 2;
            #pragma unroll
            for (int i = 0; i < 2; i++) {
                int idx = tid + i * 256;
                int j = idx >> 3, fb = idx & 7;
                int src = j * 832 + 64 + ca * 32 + fb * 4;
                *(uint4*)&sBh[j * 36 + fb * 4] = *(const uint4*)(wph + src);
                *(uint4*)&sBl[j * 36 + fb * 4] = *(const uint4*)(wpl + src);
            }
            #pragma unroll
            for (int m = 1; m < 3; m++) {
                int koff = 64 + m * 256 + ca * 32;
                #pragma unroll
                for (int i = 0; i < 2; i++) {
                    int idx = tid + i * 256;
                    int j = idx >> 3, fb = idx & 7;
                    int src = j * 832 + koff + fb * 4;
                    *(uint4*)&sBh[m * 2304 + j * 36 + fb * 4] = *(const uint4*)(wph + src);
                }
            }
        }
        __syncthreads();
        #pragma unroll
        for (int ks = 0; ks < 4; ks++) {
            int k0 = ks * 8;
            int ra = (mrow + gid) * 36 + k0 + tq;
            int rb = (mrow + gid + 8) * 36 + k0 + tq;
            uint32_t ah0 = sAh[ra], ah1 = sAh[rb], ah2 = sAh[ra + 4], ah3 = sAh[rb + 4];
            uint32_t al0 = sAl[ra], al1 = sAl[rb], al2 = sAl[ra + 4], al3 = sAl[rb + 4];
            if (isX) {
                #pragma unroll
                for (int nt = 0; nt < 8; nt++) {
                    int nb = (nt * 8 + gid) * 36 + k0 + tq;
                    mma_tf32(c1[nt][0], c1[nt][1], c1[nt][2], c1[nt][3],
                             ah0, ah1, ah2, ah3, sBh[nb], sBh[nb + 4]);
                }
            } else {
                #pragma unroll
                for (int nt = 0; nt < 8; nt++) {
                    int nb = (nt * 8 + gid) * 36 + k0 + tq;
                    uint32_t bh0 = sBh[nb], bh1 = sBh[nb + 4];
                    uint32_t bl0 = sBl[nb], bl1 = sBl[nb + 4];
                    MMA3(c1[nt], ah0, ah1, ah2, ah3, al0, al1, al2, al3, bh0, bh1, bl0, bl1);
                    mma_tf32(c2[nt][0], c2[nt][1], c2[nt][2], c2[nt][3],
                             ah0, ah1, ah2, ah3, sBh[nb + 2304], sBh[nb + 2304 + 4]);
                    mma_tf32(c3[nt][0], c3[nt][1], c3[nt][2], c3[nt][3],
                             ah0, ah1, ah2, ah3, sBh[nb + 4608], sBh[nb + 4608 + 4]);
                }
            }
        }
    }

    // combine in-place into c1: c1 + amp*c2 + att*c3 + bp
    {
        float a0 = s_amp[mrow + gid], t0 = s_att[mrow + gid];
        float a1 = s_amp[mrow + gid + 8], t1 = s_att[mrow + gid + 8];
        #pragma unroll
        for (int nt = 0; nt < 8; nt++) {
            int col = nt * 8 + 2 * tq;
            c1[nt][0] += a0 * c2[nt][0] + t0 * c3[nt][0] + s_bp[col];
            c1[nt][1] += a0 * c2[nt][1] + t0 * c3[nt][1] + s_bp[col + 1];
            c1[nt][2] += a1 * c2[nt][2] + t1 * c3[nt][2] + s_bp[col];
            c1[nt][3] += a1 * c2[nt][3] + t1 * c3[nt][3] + s_bp[col + 1];
        }
    }

    // ---------- phase 2: lin GEMM (3xTF32), K=64 in 2 chunks of 32 ----------
    #pragma unroll
    for (int nt = 0; nt < 8; nt++)
        #pragma unroll
        for (int q = 0; q < 4; q++) c3[nt][q] = 0.f;

    for (int ch2 = 0; ch2 < 2; ch2++) {
        __syncthreads();
        #pragma unroll
        for (int nt2 = 0; nt2 < 4; nt2++) {
            int nt = ch2 * 4 + nt2;
            int col = nt * 8 + 2 * tq;
            int lc = col - ch2 * 32;
            int r0 = (mrow + gid) * 36, r1 = (mrow + gid + 8) * 36;
            uint32_t h, l;
            tf32_split(c1[nt][0], h, l); sAh[r0 + lc]     = h; sAl[r0 + lc]     = l;
            tf32_split(c1[nt][1], h, l); sAh[r0 + lc + 1] = h; sAl[r0 + lc + 1] = l;
            tf32_split(c1[nt][2], h, l); sAh[r1 + lc]     = h; sAl[r1 + lc]     = l;
            tf32_split(c1[nt][3], h, l); sAh[r1 + lc + 1] = h; sAl[r1 + lc + 1] = l;
        }
        #pragma unroll
        for (int i = 0; i < 2; i++) {
            int idx = tid + i * 256;
            int j = idx >> 3, fb = idx & 7;
            int src = j * 64 + ch2 * 32 + fb * 4;
            *(uint4*)&sBh[j * 36 + fb * 4] = *(const uint4*)(lwh + src);
            *(uint4*)&sBl[j * 36 + fb * 4] = *(const uint4*)(lwl + src);
        }
        __syncthreads();
        #pragma unroll
        for (int ks = 0; ks < 4; ks++) {
            int k0 = ks * 8;
            int ra = (mrow + gid) * 36 + k0 + tq;
            int rb = (mrow + gid + 8) * 36 + k0 + tq;
            uint32_t ah0 = sAh[ra], ah1 = sAh[rb], ah2 = sAh[ra + 4], ah3 = sAh[rb + 4];
            uint32_t al0 = sAl[ra], al1 = sAl[rb], al2 = sAl[ra + 4], al3 = sAl[rb + 4];
            #pragma unroll
            for (int nt = 0; nt < 8; nt++) {
                int nb = (nt * 8 + gid) * 36 + k0 + tq;
                uint32_t bh0 = sBh[nb], bh1 = sBh[nb + 4];
                uint32_t bl0 = sBl[nb], bl1 = sBl[nb + 4];
                MMA3(c3[nt], ah0, ah1, ah2, ah3, al0, al1, al2, al3, bh0, bh1, bl0, bl1);
            }
        }
    }

    // epilogue: relu(c3 + bl) -> gmem
    int grow0 = row0 + mrow + gid;
    int grow1 = grow0 + 8;
    #pragma unroll
    for (int nt = 0; nt < 8; nt++) {
        int col = nt * 8 + 2 * tq;
        float bl0 = s_bl[col], bl1 = s_bl[col + 1];
        if (grow0 < NN) {
            float2 o = make_float2(fmaxf(c3[nt][0] + bl0, 0.f), fmaxf(c3[nt][1] + bl1, 0.f));
            *(float2*)(Xn + (size_t)grow0 * 64 + col) = o;
        }
        if (grow1 < NN) {
            float2 o = make_float2(fmaxf(c3[nt][2] + bl0, 0.f), fmaxf(c3[nt][3] + bl1, 0.f));
            *(float2*)(Xn + (size_t)grow1 * 64 + col) = o;
        }
    }
}

// ---------------- pooling + MLP ----------------
__global__ void k_pool(const float* __restrict__ X, const int* __restrict__ batch) {
    int idx = blockIdx.x * blockDim.x + threadIdx.x;
    int f = idx & 63;
    int chunk = idx >> 6;
    int n0 = chunk * 8;
    if (n0 >= NN) return;
    int ne = n0 + 8 < NN ? n0 + 8 : NN;
    int cg = batch[n0];
    float acc = 0.f;
    int cnt = 0;
    for (int n = n0; n < ne; n++) {
        int g = batch[n];
        if (g != cg) {
            atomicAdd(&d_pool[cg * 64 + f], acc);
            if (f == 0) atomicAdd(&d_cnt[cg], cnt);
            acc = 0.f; cnt = 0; cg = g;
        }
        acc += X[(size_t)n * 64 + f];
        cnt++;
    }
    atomicAdd(&d_pool[cg * 64 + f], acc);
    if (f == 0) atomicAdd(&d_cnt[cg], cnt);
}

__global__ void k_mlp(const float* __restrict__ W1, const float* __restrict__ b1,
                      const float* __restrict__ W2, const float* __restrict__ b2,
                      float* __restrict__ out) {
    __shared__ float gv[64], hv[64];
    int g = blockIdx.x, t = threadIdx.x;
    int c = d_cnt[g];
    float cntf = (float)(c > 1 ? c : 1);
    gv[t] = d_pool[g * 64 + t] / cntf;
    __syncthreads();
    float a = b1[t];
    #pragma unroll 8
    for (int k = 0; k < 64; k++) a += W1[t * 64 + k] * gv[k];
    hv[t] = fmaxf(a, 0.f);
    __syncthreads();
    if (t < 16) {
        float o = b2[t];
        #pragma unroll 8
        for (int k = 0; k < 64; k++) o += W2[t * 64 + k] * hv[k];
        out[g * 16 + t] = o;
    }
}

// ---------------- launch ----------------
extern "C" void kernel_launch(void* const* d_in, const int* in_sizes, int n_in,
                              void* d_out, int out_size) {
    const float* x      = (const float*)d_in[0];
    const int*   ei     = (const int*)d_in[1];
    const int*   batch  = (const int*)d_in[2];
    const float* pre_w  = (const float*)d_in[3];
    const float* pre_b  = (const float*)d_in[4];
    const float* post_w = (const float*)d_in[5];
    const float* post_b = (const float*)d_in[6];
    const float* lin_w  = (const float*)d_in[7];
    const float* lin_b  = (const float*)d_in[8];
    const float* mw1    = (const float*)d_in[9];
    const float* mb1    = (const float*)d_in[10];
    const float* mw2    = (const float*)d_in[11];
    const float* mb2    = (const float*)d_in[12];
    float* out = (float*)d_out;
    const int* srcp = ei;
    const int* dstp = ei + NE;

    void *pa, *pb, *pw;
    cudaGetSymbolAddress(&pa, d_xa);
    cudaGetSymbolAddress(&pb, d_xb);
    float* xa = (float*)pa;
    float* xb = (float*)pb;
    uint32_t *wph, *wpl, *pwh, *pwl, *lwh, *lwl;
    cudaGetSymbolAddress(&pw, d_wph); wph = (uint32_t*)pw;
    cudaGetSymbolAddress(&pw, d_wpl); wpl = (uint32_t*)pw;
    cudaGetSymbolAddress(&pw, d_pwh); pwh = (uint32_t*)pw;
    cudaGetSymbolAddress(&pw, d_pwl); pwl = (uint32_t*)pw;
    cudaGetSymbolAddress(&pw, d_lwh); lwh = (uint32_t*)pw;
    cudaGetSymbolAddress(&pw, d_lwl); lwl = (uint32_t*)pw;

    cudaFuncSetAttribute(k_post_mma_sync, cudaFuncAttributeMaxDynamicSharedMemorySize, POST_SMEM);
    cudaFuncSetAttribute(k_pre_mma, cudaFuncAttributeMaxDynamicSharedMemorySize, PRE_SMEM);

    k_init<<<(NN + 255) / 256, 256>>>();
    k_splitw<<<312, 256>>>(pre_w, post_w, lin_w);
    k_degree<<<(NE + 255) / 256, 256>>>(dstp);
    k_scan1<<<NB_SCAN, 256>>>();
    k_scan3<<<NB_SCAN, 256>>>();
    k_fill<<<(NE + 255) / 256, 256>>>(srcp, dstp);

    const float* cur = x;
    float* nxt = xa;
    for (int l = 0; l < 3; l++) {
        k_pre_mma<<<(NN + 127) / 128, 256, PRE_SMEM>>>(cur, pwh + l * 8192, pwl + l * 8192,
                                                       pre_b + l * 64);
        k_aggr<<<(NN * 32 + 255) / 256, 256>>>();
        k_post_mma_sync<<<(NN + 127) / 128, 256, POST_SMEM>>>(
            cur, wph + l * 53248, wpl + l * 53248, post_b + l * 64,
            lwh + l * 4096, lwl + l * 4096, lin_b + l * 64, nxt);
        cur = nxt;
        nxt = (nxt == xa) ? xb : xa;
    }
    k_pool<<<(((NN + 7) / 8) * 64 + 255) / 256, 256>>>(cur, batch);
    k_mlp<<<NG, 64>>>(mw1, mb1, mw2, mb2, out);
}